// round 16
// baseline (speedup 1.0000x reference)
#include <cuda_runtime.h>
#include <cuda_fp16.h>
#include <cstdint>

// ---------------------------------------------------------------------------
// FullGapModel collapse:
//   out[s] = sum_{i: row_seg[i]==s} (x_i^T Q x_i) / ||x_i||^2
//   Q[a,b] = sum_j weights[col_seg[j]] * SP[j,a] * SP[j,b]   (400x400, sym)
//
// Single-product fp16 scheme (R15, proven):
//   xh = fp16(x),  Qf = fp16(Q),  D = Qf * xh   (HMMA fp16, fp32 accum)
//   v  = (2x - xh)^T D,   out[seg] += v / ||x||^2
// R16: X->fp16 conversion moved INTO gap_mma as a per-CTA prologue (each CTA
// converts only its own 128-row slab; no cross-CTA deps). prep = build-Q only.
// Pipeline: flat 91-slice loop, 5-stage cp.async ring, prefetch distance 4,
// one __syncthreads per slice, no drains.
// ---------------------------------------------------------------------------

#define D_DIM     400
#define KPADX     416          // K padded: 13 slices of 32
#define NSLICE    13
#define NPADQ     448          // Q padded rows: 7 chunks of 64
#define NCHUNK    7
#define TOTS      (NSLICE * NCHUNK)   // 91
#define BM        128
#define BN        64
#define NROWS_PAD 100096       // 782 * 128
#define C8MAX     (KPADX / 8)  // 52

#define QTILES    (13 * 14)    // 182 (k-tiles x n-tiles)
#define KSPLIT    8
#define NQB       (QTILES * KSPLIT)   // 1456 build blocks

#define AS_ST     40                       // fp16 elems per smem row (32+8 pad)
#define A_EL      (BM * AS_ST)             // 5120
#define B_EL      (BN * AS_ST)             // 2560
#define O_AHI     0
#define O_BHI     A_EL
#define STAGE_EL  (A_EL + B_EL)            // 7680 elems = 15360 B
#define NSTG      5
#define SV_OFF    (NSTG * STAGE_EL * 2)    // bytes: 76800
#define SN_OFF    (SV_OFF + BM * 4)
#define SMEM_TOTAL (SN_OFF + BM * 4)       // 77824 B

// Static global scratch (no allocation allowed).
__device__ __align__(128) __half g_Xh[(size_t)NROWS_PAD * KPADX];
__device__ __align__(128) __half g_Qh[(size_t)NPADQ * KPADX];
__device__ __align__(128) float  g_Qpart[(size_t)KSPLIT * NPADQ * KPADX];

// ---------------- helpers --------------------------------------------------

__device__ __forceinline__ uint32_t smem_u32(const void* p) {
    uint32_t a;
    asm("{ .reg .u64 t; cvta.to.shared.u64 t, %1; cvt.u32.u64 %0, t; }"
        : "=r"(a) : "l"(p));
    return a;
}

__device__ __forceinline__ void cp16(uint32_t dst, const void* src) {
    asm volatile("cp.async.cg.shared.global [%0], [%1], 16;"
                 :: "r"(dst), "l"(src) : "memory");
}
__device__ __forceinline__ void cp_commit() {
    asm volatile("cp.async.commit_group;" ::: "memory");
}
template <int N>
__device__ __forceinline__ void cp_wait() {
    asm volatile("cp.async.wait_group %0;" :: "n"(N) : "memory");
}

__device__ __forceinline__ void ldsm_x4(uint32_t* r, uint32_t addr) {
    asm volatile("ldmatrix.sync.aligned.m8n8.x4.shared.b16 {%0,%1,%2,%3}, [%4];"
                 : "=r"(r[0]), "=r"(r[1]), "=r"(r[2]), "=r"(r[3]) : "r"(addr));
}

__device__ __forceinline__ void mma_f16(float* c, const uint32_t* a,
                                        uint32_t b0, uint32_t b1) {
    asm volatile(
        "mma.sync.aligned.m16n8k16.row.col.f32.f16.f16.f32 "
        "{%0,%1,%2,%3}, {%4,%5,%6,%7}, {%8,%9}, {%0,%1,%2,%3};"
        : "+f"(c[0]), "+f"(c[1]), "+f"(c[2]), "+f"(c[3])
        : "r"(a[0]), "r"(a[1]), "r"(a[2]), "r"(a[3]), "r"(b0), "r"(b1));
}

__device__ __forceinline__ uint32_t pack_h2(__half a, __half b) {
    __half2 t = __halves2half2(a, b);   // a in low 16 bits
    return *reinterpret_cast<uint32_t*>(&t);
}

// ---------------------------------------------------------------------------
// prep kernel: build-Q fp32 partials only (K-split x8, 1456 blocks).
// ---------------------------------------------------------------------------
__global__ __launch_bounds__(256)
void prep_kernel(const float* __restrict__ SP,
                 const float* __restrict__ W,
                 const int*  __restrict__ colseg,
                 int M) {
    __shared__ float As[32][33];
    __shared__ float Bs[32][33];

    const int tid = threadIdx.x;

    const int bq    = blockIdx.x;
    const int tile  = bq % QTILES;
    const int chunk = bq / QTILES;
    const int bx    = tile % 13;          // k tile
    const int by    = tile / 13;          // n tile
    const int a0    = by * 32;
    const int b0    = bx * 32;
    const int ty    = tid >> 4;
    const int tx    = tid & 15;

    const int csz  = (M + KSPLIT - 1) / KSPLIT;
    const int jbeg = chunk * csz;
    const int jend = (jbeg + csz < M) ? (jbeg + csz) : M;

    float c00 = 0.f, c01 = 0.f, c10 = 0.f, c11 = 0.f;

    for (int j0 = jbeg; j0 < jend; j0 += 32) {
        #pragma unroll
        for (int e = tid; e < 1024; e += 256) {
            int jj  = e >> 5;
            int col = e & 31;
            int j   = j0 + jj;
            float av = 0.f, bv = 0.f;
            if (j < jend) {
                float wp = W[colseg[j]];
                int a = a0 + col;
                int b = b0 + col;
                if (a < D_DIM) av = SP[(size_t)j * D_DIM + a] * wp;
                if (b < D_DIM) bv = SP[(size_t)j * D_DIM + b];
            }
            As[jj][col] = av;
            Bs[jj][col] = bv;
        }
        __syncthreads();

        #pragma unroll
        for (int jj = 0; jj < 32; ++jj) {
            float a0r = As[jj][ty];
            float a1r = As[jj][ty + 16];
            float b0r = Bs[jj][tx];
            float b1r = Bs[jj][tx + 16];
            c00 = fmaf(a0r, b0r, c00);
            c01 = fmaf(a0r, b1r, c01);
            c10 = fmaf(a1r, b0r, c10);
            c11 = fmaf(a1r, b1r, c11);
        }
        __syncthreads();
    }

    float* qp = g_Qpart + (size_t)chunk * (NPADQ * KPADX);
    qp[(size_t)(a0 + ty     ) * KPADX + (b0 + tx     )] = c00;
    qp[(size_t)(a0 + ty     ) * KPADX + (b0 + tx + 16)] = c01;
    qp[(size_t)(a0 + ty + 16) * KPADX + (b0 + tx     )] = c10;
    qp[(size_t)(a0 + ty + 16) * KPADX + (b0 + tx + 16)] = c11;
}

// ---------------------------------------------------------------------------
// convert_q: sum the 8 fp32 partials -> fp16 Q. Block 0 also zeroes the
// output vector (harness poisons it with 0xAA).
// ---------------------------------------------------------------------------
__global__ __launch_bounds__(KPADX)
void convert_q_kernel(float* __restrict__ out, int nout) {
    const int a = blockIdx.x;     // 0..447
    const int b = threadIdx.x;    // 0..415
    float s = 0.f;
    #pragma unroll
    for (int c = 0; c < KSPLIT; ++c)
        s += g_Qpart[(size_t)c * (NPADQ * KPADX) + (size_t)a * KPADX + b];
    g_Qh[(size_t)a * KPADX + b] = __float2half_rn(s);
    if (blockIdx.x == 0)
        for (int i = b; i < nout; i += KPADX) out[i] = 0.f;
}

// ---------------------------------------------------------------------------
// Main kernel: 256 threads (8 warps: 4 M-slices x 2 N-slices).
// Prologue: convert own 128-row X slab fp32 -> fp16 into g_Xh (padded).
// Then the R15 pipeline: flat 91 (nc, sl) loop, 5-stage cp.async ring,
// prefetch distance 4, one __syncthreads per slice, no drains.
// ---------------------------------------------------------------------------
__global__ __launch_bounds__(256, 2)
void gap_mma_kernel(const float* __restrict__ X,
                    const int*  __restrict__ rowseg,
                    float* __restrict__ out,
                    int N) {
    extern __shared__ __align__(16) char smem[];
    float* const sv = reinterpret_cast<float*>(smem + SV_OFF);
    float* const sn = reinterpret_cast<float*>(smem + SN_OFF);

    const int tid  = threadIdx.x;
    const int lane = tid & 31;
    const int wid  = tid >> 5;
    const int wm   = wid & 3;            // M slice 0..3 (32 rows)
    const int wn   = wid >> 2;           // N slice 0..1 (32 cols)
    const int g    = lane >> 2;
    const int tg   = lane & 3;

    const uint32_t s_u32 = smem_u32(smem);

    const int arow_l = lane & 15;
    const int acol_l = (lane >> 4) * 8;
    const int brow_l = (lane & 7) + ((lane >> 4) << 3);
    const int bcol_l = ((lane >> 3) & 1) * 8;

    const size_t row0 = (size_t)blockIdx.x * BM;

    if (tid < BM) { sv[tid] = 0.f; sn[tid] = 0.f; }

    // ---- prologue: convert own A slab  X[row0:+128, :] -> g_Xh (fp16) ----
    {
        const int rr = tid >> 6;         // 0..3
        const int cc = tid & 63;         // 0..63
        if (cc < C8MAX) {
            const bool cvalid = (cc < (D_DIM / 8));   // cols cc*8..+7 < 400
            #pragma unroll 4
            for (int r = rr; r < BM; r += 4) {
                const size_t row = row0 + (size_t)r;
                uint4 hv = make_uint4(0u, 0u, 0u, 0u);
                if (row < (size_t)N && cvalid) {
                    const float4* p = reinterpret_cast<const float4*>(
                        X + row * D_DIM + cc * 8);
                    float4 v0 = p[0], v1 = p[1];
                    float f[8] = { v0.x, v0.y, v0.z, v0.w,
                                   v1.x, v1.y, v1.z, v1.w };
                    __half h[8];
                    #pragma unroll
                    for (int q = 0; q < 8; ++q) h[q] = __float2half_rn(f[q]);
                    hv = make_uint4(pack_h2(h[0], h[1]), pack_h2(h[2], h[3]),
                                    pack_h2(h[4], h[5]), pack_h2(h[6], h[7]));
                }
                *reinterpret_cast<uint4*>(g_Xh + row * KPADX + cc * 8) = hv;
            }
        }
    }
    __syncthreads();   // g_Xh slab visible to whole CTA before staging

    float vp[4] = { 0.f, 0.f, 0.f, 0.f };
    float np[4] = { 0.f, 0.f, 0.f, 0.f };

    const int ra = tid >> 2;
    const int ca = tid & 3;

    // stage slice (sl of chunk nc) into ring buffer buf (3 cp16 per thread)
    auto stage = [&](int sl, int nc, int buf) {
        const int ks = sl * 32;
        const uint32_t sb = s_u32 + (uint32_t)buf * (STAGE_EL * 2);
        const __half* Bh = g_Qh + (size_t)(nc * BN) * KPADX;
        cp16(sb + (O_AHI + ra * AS_ST + ca * 8) * 2,
             g_Xh + (row0 + ra) * KPADX + ks + ca * 8);
        cp16(sb + (O_AHI + (ra + 64) * AS_ST + ca * 8) * 2,
             g_Xh + (row0 + ra + 64) * KPADX + ks + ca * 8);
        cp16(sb + (O_BHI + ra * AS_ST + ca * 8) * 2,
             Bh + (size_t)ra * KPADX + ks + ca * 8);
        cp_commit();
    };

    float c[2][4][4];
    #pragma unroll
    for (int mt = 0; mt < 2; ++mt)
        #pragma unroll
        for (int nt = 0; nt < 4; ++nt)
            #pragma unroll
            for (int q = 0; q < 4; ++q) c[mt][nt][q] = 0.f;

    // prologue: stage gs=0..3 into bufs 0..3
    stage(0, 0, 0);
    stage(1, 0, 1);
    stage(2, 0, 2);
    stage(3, 0, 3);
    cp_wait<3>();
    __syncthreads();

    int sl_c = 0, nc_c = 0, buf_c = 0;   // compute cursor (gs)
    int sl_p = 4, nc_p = 0, buf_p = 4;   // prefetch cursor (gs+4)

    #pragma unroll 1
    for (int gs = 0; gs < TOTS; ++gs) {
        const bool do_stage = (gs + 4 < TOTS);
        if (do_stage) stage(sl_p, nc_p, buf_p);

        // ---- compute on buf_c ----
        const uint32_t sb = s_u32 + (uint32_t)buf_c * (STAGE_EL * 2);
        #pragma unroll
        for (int kk = 0; kk < 2; ++kk) {
            uint32_t a[2][4], b[2][4];
            #pragma unroll
            for (int mt = 0; mt < 2; ++mt) {
                uint32_t ao = (uint32_t)(((wm * 32 + 16 * mt + arow_l) * AS_ST
                                          + kk * 16 + acol_l) * 2);
                ldsm_x4(a[mt], sb + O_AHI * 2 + ao);
            }
            #pragma unroll
            for (int nh = 0; nh < 2; ++nh) {
                uint32_t bo = (uint32_t)(((wn * 32 + 16 * nh + brow_l) * AS_ST
                                          + kk * 16 + bcol_l) * 2);
                ldsm_x4(b[nh], sb + O_BHI * 2 + bo);
            }
            #pragma unroll
            for (int mt = 0; mt < 2; ++mt)
                #pragma unroll
                for (int nt = 0; nt < 4; ++nt)
                    mma_f16(c[mt][nt], a[mt],
                            b[nt >> 1][(nt & 1) * 2],
                            b[nt >> 1][(nt & 1) * 2 + 1]);
        }

        // ---- end of chunk: fold with u = 2x - fp16(x), reset accum ----
        if (sl_c == NSLICE - 1) {
            #pragma unroll
            for (int mt = 0; mt < 2; ++mt) {
                const int    r0l = wm * 32 + 16 * mt + g;
                const size_t R0  = row0 + (size_t)r0l;
                #pragma unroll
                for (int nt = 0; nt < 4; ++nt) {
                    int C0 = nc_c * 64 + wn * 32 + 8 * nt + 2 * tg;
                    if (C0 < D_DIM) {
                        if (R0 < (size_t)N) {
                            float2 x0 = __ldg(reinterpret_cast<const float2*>(
                                X + R0 * D_DIM + C0));
                            float u0x = 2.f * x0.x -
                                __half2float(__float2half_rn(x0.x));
                            float u0y = 2.f * x0.y -
                                __half2float(__float2half_rn(x0.y));
                            vp[2 * mt] = fmaf(u0x, c[mt][nt][0],
                                          fmaf(u0y, c[mt][nt][1], vp[2 * mt]));
                            np[2 * mt] = fmaf(x0.x, x0.x,
                                          fmaf(x0.y, x0.y, np[2 * mt]));
                        }
                        if (R0 + 8 < (size_t)N) {
                            float2 x1 = __ldg(reinterpret_cast<const float2*>(
                                X + (R0 + 8) * D_DIM + C0));
                            float u1x = 2.f * x1.x -
                                __half2float(__float2half_rn(x1.x));
                            float u1y = 2.f * x1.y -
                                __half2float(__float2half_rn(x1.y));
                            vp[2 * mt + 1] = fmaf(u1x, c[mt][nt][2],
                                              fmaf(u1y, c[mt][nt][3], vp[2 * mt + 1]));
                            np[2 * mt + 1] = fmaf(x1.x, x1.x,
                                              fmaf(x1.y, x1.y, np[2 * mt + 1]));
                        }
                    }
                    #pragma unroll
                    for (int q = 0; q < 4; ++q) c[mt][nt][q] = 0.f;
                }
            }
        }

        // ---- wait so buffer gs+1 is complete, then publish ----
        if (gs + 4 < TOTS)      cp_wait<3>();
        else if (gs + 3 < TOTS) cp_wait<2>();
        else if (gs + 2 < TOTS) cp_wait<1>();
        else                    cp_wait<0>();
        __syncthreads();

        ++buf_c; if (buf_c == NSTG) buf_c = 0;
        ++buf_p; if (buf_p == NSTG) buf_p = 0;
        ++sl_c;  if (sl_c == NSLICE) { sl_c = 0; ++nc_c; }
        ++sl_p;  if (sl_p == NSLICE) { sl_p = 0; ++nc_p; }
    }

    // reduce across the 4 lanes sharing each row, then smem accumulate
    #pragma unroll
    for (int i = 0; i < 4; ++i) {
        vp[i] += __shfl_xor_sync(0xFFFFFFFFu, vp[i], 1);
        vp[i] += __shfl_xor_sync(0xFFFFFFFFu, vp[i], 2);
        np[i] += __shfl_xor_sync(0xFFFFFFFFu, np[i], 1);
        np[i] += __shfl_xor_sync(0xFFFFFFFFu, np[i], 2);
    }
    if (tg == 0) {
        #pragma unroll
        for (int i = 0; i < 4; ++i) {
            int mt = i >> 1, hi = i & 1;
            int r  = wm * 32 + 16 * mt + 8 * hi + g;
            atomicAdd(&sv[r], vp[i]);
            atomicAdd(&sn[r], np[i]);
        }
    }
    __syncthreads();

    if (tid < BM) {
        size_t row = row0 + (size_t)tid;
        if (row < (size_t)N) {
            float nr = sn[tid];
            if (nr > 0.f)
                atomicAdd(out + __ldg(rowseg + row), sv[tid] / nr);
        }
    }
}

// ---------------------------------------------------------------------------
extern "C" void kernel_launch(void* const* d_in, const int* in_sizes, int n_in,
                              void* d_out, int out_size) {
    const float* X      = (const float*)d_in[0];
    const float* SP     = (const float*)d_in[1];
    const float* W      = (const float*)d_in[2];
    const int*   rowseg = (const int*)  d_in[4];
    const int*   colseg = (const int*)  d_in[5];
    float* out = (float*)d_out;

    const int N = in_sizes[4];   // environments
    const int M = in_sizes[5];   // support points

    // 1) build-Q fp32 partials (small, fast)
    prep_kernel<<<NQB, 256>>>(SP, W, colseg, M);

    // 2) reduce Q partials -> fp16; also zero the output vector
    convert_q_kernel<<<NPADQ, KPADX>>>(out, out_size);

    // 3) main kernel: per-CTA X->fp16 prologue + GEMM + quadratic form
    //    + segment reduction
    cudaFuncSetAttribute(gap_mma_kernel,
                         cudaFuncAttributeMaxDynamicSharedMemorySize, SMEM_TOTAL);
    int ntiles = (N + BM - 1) / BM;
    gap_mma_kernel<<<ntiles, 256, SMEM_TOTAL>>>(X, rowseg, out, N);
}

// round 17
// speedup vs baseline: 1.1514x; 1.1514x over previous
#include <cuda_runtime.h>
#include <cuda_fp16.h>
#include <cstdint>

// ---------------------------------------------------------------------------
// FullGapModel collapse:
//   out[s] = sum_{i: row_seg[i]==s} (x_i^T Q x_i) / ||x_i||^2
//   Q[a,b] = sum_j weights[col_seg[j]] * SP[j,a] * SP[j,b]   (400x400, sym)
//
// Single-product fp16 scheme (R15, proven):
//   xh = fp16(x),  Qf = fp16(Q),  D = Qf * xh   (HMMA fp16, fp32 accum)
//   v  = (2x - xh)^T D,   out[seg] += v / ||x||^2
// R17: prep = { 392 build-Q blocks (64x64 tiles, 4x4 reg blocking, 2:1
// FMA:LDS) + 25024 split-X blocks } fused & concurrent; gap_mma reverted to
// the R15 version (5-stage cp.async ring, prefetch dist 4, 1 barrier/slice).
// ---------------------------------------------------------------------------

#define D_DIM     400
#define KPADX     416          // K padded: 13 slices of 32
#define NSLICE    13
#define NPADQ     448          // Q padded rows: 7 chunks of 64
#define NCHUNK    7
#define TOTS      (NSLICE * NCHUNK)   // 91
#define BM        128
#define BN        64
#define NROWS_PAD 100096       // 782 * 128
#define C8MAX     (KPADX / 8)  // 52

#define QT2       49           // 7x7 64x64 tiles covering [448 x 448)
#define KSPLIT    8
#define NQB       (QT2 * KSPLIT)      // 392 build blocks
#define NSB       (NROWS_PAD / 4)     // 25024 split blocks

#define AS_ST     40                       // fp16 elems per smem row (32+8 pad)
#define A_EL      (BM * AS_ST)             // 5120
#define B_EL      (BN * AS_ST)             // 2560
#define O_AHI     0
#define O_BHI     A_EL
#define STAGE_EL  (A_EL + B_EL)            // 7680 elems = 15360 B
#define NSTG      5
#define SV_OFF    (NSTG * STAGE_EL * 2)    // bytes: 76800
#define SN_OFF    (SV_OFF + BM * 4)
#define SMEM_TOTAL (SN_OFF + BM * 4)       // 77824 B

// Static global scratch (no allocation allowed).
__device__ __align__(128) __half g_Xh[(size_t)NROWS_PAD * KPADX];
__device__ __align__(128) __half g_Qh[(size_t)NPADQ * KPADX];
__device__ __align__(128) float  g_Qpart[(size_t)KSPLIT * NPADQ * KPADX];

// ---------------- helpers --------------------------------------------------

__device__ __forceinline__ uint32_t smem_u32(const void* p) {
    uint32_t a;
    asm("{ .reg .u64 t; cvta.to.shared.u64 t, %1; cvt.u32.u64 %0, t; }"
        : "=r"(a) : "l"(p));
    return a;
}

__device__ __forceinline__ void cp16(uint32_t dst, const void* src) {
    asm volatile("cp.async.cg.shared.global [%0], [%1], 16;"
                 :: "r"(dst), "l"(src) : "memory");
}
__device__ __forceinline__ void cp_commit() {
    asm volatile("cp.async.commit_group;" ::: "memory");
}
template <int N>
__device__ __forceinline__ void cp_wait() {
    asm volatile("cp.async.wait_group %0;" :: "n"(N) : "memory");
}

__device__ __forceinline__ void ldsm_x4(uint32_t* r, uint32_t addr) {
    asm volatile("ldmatrix.sync.aligned.m8n8.x4.shared.b16 {%0,%1,%2,%3}, [%4];"
                 : "=r"(r[0]), "=r"(r[1]), "=r"(r[2]), "=r"(r[3]) : "r"(addr));
}

__device__ __forceinline__ void mma_f16(float* c, const uint32_t* a,
                                        uint32_t b0, uint32_t b1) {
    asm volatile(
        "mma.sync.aligned.m16n8k16.row.col.f32.f16.f16.f32 "
        "{%0,%1,%2,%3}, {%4,%5,%6,%7}, {%8,%9}, {%0,%1,%2,%3};"
        : "+f"(c[0]), "+f"(c[1]), "+f"(c[2]), "+f"(c[3])
        : "r"(a[0]), "r"(a[1]), "r"(a[2]), "r"(a[3]), "r"(b0), "r"(b1));
}

__device__ __forceinline__ uint32_t pack_h2(__half a, __half b) {
    __half2 t = __halves2half2(a, b);   // a in low 16 bits
    return *reinterpret_cast<uint32_t*>(&t);
}

// ---------------------------------------------------------------------------
// prep kernel:
//   blocks [0, NQB): build-Q fp32 partials, 64x64 tile, 4x4 register
//     blocking per thread (16x16 thread grid), 16-row j-tiles.
//   blocks [NQB, NQB+NSB): X -> fp16 conversion (4 rows per block).
// The two halves are independent and overlap on the machine.
// ---------------------------------------------------------------------------
__global__ __launch_bounds__(256)
void prep_kernel(const float* __restrict__ X,
                 const float* __restrict__ SP,
                 const float* __restrict__ W,
                 const int*  __restrict__ colseg,
                 int N, int M) {
    __shared__ float As[16][68];
    __shared__ float Bs[16][68];

    const int tid = threadIdx.x;

    if (blockIdx.x < NQB) {
        // ---------------- build-Q partial (64x64 tile) ----------------
        const int bq    = blockIdx.x;
        const int tile  = bq % QT2;
        const int chunk = bq / QT2;
        const int bx    = tile % 7;           // k tile (64 cols)
        const int by    = tile / 7;           // n tile (64 rows)
        const int a0    = by * 64;
        const int b0    = bx * 64;
        const int ty    = tid >> 4;           // 0..15
        const int tx    = tid & 15;           // 0..15

        const int csz  = (M + KSPLIT - 1) / KSPLIT;
        const int jbeg = chunk * csz;
        const int jend = (jbeg + csz < M) ? (jbeg + csz) : M;

        float c[4][4];
        #pragma unroll
        for (int i = 0; i < 4; ++i)
            #pragma unroll
            for (int j = 0; j < 4; ++j) c[i][j] = 0.f;

        // load mapping: jj = tid>>4 (row in j-tile), c4 = tid&15 (float4 col)
        const int jj_l = tid >> 4;
        const int c4_l = tid & 15;

        for (int j0 = jbeg; j0 < jend; j0 += 16) {
            const int j = j0 + jj_l;
            float4 av = make_float4(0.f, 0.f, 0.f, 0.f);
            float4 bv = make_float4(0.f, 0.f, 0.f, 0.f);
            if (j < jend) {
                const float wp = W[colseg[j]];
                const int a = a0 + 4 * c4_l;
                const int b = b0 + 4 * c4_l;
                if (a < D_DIM) {
                    av = *reinterpret_cast<const float4*>(
                        SP + (size_t)j * D_DIM + a);
                    av.x *= wp; av.y *= wp; av.z *= wp; av.w *= wp;
                }
                if (b < D_DIM)
                    bv = *reinterpret_cast<const float4*>(
                        SP + (size_t)j * D_DIM + b);
            }
            *reinterpret_cast<float4*>(&As[jj_l][4 * c4_l]) = av;
            *reinterpret_cast<float4*>(&Bs[jj_l][4 * c4_l]) = bv;
            __syncthreads();

            #pragma unroll
            for (int jj = 0; jj < 16; ++jj) {
                float ar[4], br[4];
                #pragma unroll
                for (int i = 0; i < 4; ++i) ar[i] = As[jj][ty + 16 * i];
                #pragma unroll
                for (int j2 = 0; j2 < 4; ++j2) br[j2] = Bs[jj][tx + 16 * j2];
                #pragma unroll
                for (int i = 0; i < 4; ++i)
                    #pragma unroll
                    for (int j2 = 0; j2 < 4; ++j2)
                        c[i][j2] = fmaf(ar[i], br[j2], c[i][j2]);
            }
            __syncthreads();
        }

        float* qp = g_Qpart + (size_t)chunk * (NPADQ * KPADX);
        #pragma unroll
        for (int i = 0; i < 4; ++i) {
            const int arow = a0 + ty + 16 * i;     // < 448 always
            #pragma unroll
            for (int j2 = 0; j2 < 4; ++j2) {
                const int bcol = b0 + tx + 16 * j2;
                if (bcol < KPADX)
                    qp[(size_t)arow * KPADX + bcol] = c[i][j2];
            }
        }
    } else {
        // ---------------- X -> fp16 ----------------
        const int bs = blockIdx.x - NQB;
        const int r  = bs * 4 + (tid >> 6);
        const int c8 = tid & 63;
        if (c8 >= C8MAX || r >= NROWS_PAD) return;
        uint4 hv = make_uint4(0u, 0u, 0u, 0u);
        if (r < N && c8 < (D_DIM / 8)) {
            const float4* p = reinterpret_cast<const float4*>(
                X + (size_t)r * D_DIM + c8 * 8);
            float4 v0 = p[0], v1 = p[1];
            float f[8] = { v0.x, v0.y, v0.z, v0.w, v1.x, v1.y, v1.z, v1.w };
            __half h[8];
            #pragma unroll
            for (int q = 0; q < 8; ++q) h[q] = __float2half_rn(f[q]);
            hv = make_uint4(pack_h2(h[0], h[1]), pack_h2(h[2], h[3]),
                            pack_h2(h[4], h[5]), pack_h2(h[6], h[7]));
        }
        *reinterpret_cast<uint4*>(g_Xh + (size_t)r * KPADX + c8 * 8) = hv;
    }
}

// ---------------------------------------------------------------------------
// convert_q: sum the 8 fp32 partials -> fp16 Q. Block 0 also zeroes the
// output vector (harness poisons it with 0xAA).
// ---------------------------------------------------------------------------
__global__ __launch_bounds__(KPADX)
void convert_q_kernel(float* __restrict__ out, int nout) {
    const int a = blockIdx.x;     // 0..447
    const int b = threadIdx.x;    // 0..415
    float s = 0.f;
    #pragma unroll
    for (int c = 0; c < KSPLIT; ++c)
        s += g_Qpart[(size_t)c * (NPADQ * KPADX) + (size_t)a * KPADX + b];
    g_Qh[(size_t)a * KPADX + b] = __float2half_rn(s);
    if (blockIdx.x == 0)
        for (int i = b; i < nout; i += KPADX) out[i] = 0.f;
}

// ---------------------------------------------------------------------------
// Main kernel (R15, proven): 256 threads (8 warps: 4 M-slices x 2 N-slices).
// Flat loop over 91 (nc, sl) pairs; 5-stage cp.async ring, prefetch
// distance 4, one __syncthreads per slice, no drains.
// Single fp16 product: per kk, 4 LDSM feed 8 HMMA.
// ---------------------------------------------------------------------------
__global__ __launch_bounds__(256, 2)
void gap_mma_kernel(const float* __restrict__ X,
                    const int*  __restrict__ rowseg,
                    float* __restrict__ out,
                    int N) {
    extern __shared__ __align__(16) char smem[];
    float* const sv = reinterpret_cast<float*>(smem + SV_OFF);
    float* const sn = reinterpret_cast<float*>(smem + SN_OFF);

    const int tid  = threadIdx.x;
    const int lane = tid & 31;
    const int wid  = tid >> 5;
    const int wm   = wid & 3;            // M slice 0..3 (32 rows)
    const int wn   = wid >> 2;           // N slice 0..1 (32 cols)
    const int g    = lane >> 2;
    const int tg   = lane & 3;

    const uint32_t s_u32 = smem_u32(smem);

    const int arow_l = lane & 15;
    const int acol_l = (lane >> 4) * 8;
    const int brow_l = (lane & 7) + ((lane >> 4) << 3);
    const int bcol_l = ((lane >> 3) & 1) * 8;

    const size_t row0 = (size_t)blockIdx.x * BM;

    if (tid < BM) { sv[tid] = 0.f; sn[tid] = 0.f; }

    float vp[4] = { 0.f, 0.f, 0.f, 0.f };
    float np[4] = { 0.f, 0.f, 0.f, 0.f };

    const int ra = tid >> 2;
    const int ca = tid & 3;

    // stage slice (sl of chunk nc) into ring buffer buf (3 cp16 per thread)
    auto stage = [&](int sl, int nc, int buf) {
        const int ks = sl * 32;
        const uint32_t sb = s_u32 + (uint32_t)buf * (STAGE_EL * 2);
        const __half* Bh = g_Qh + (size_t)(nc * BN) * KPADX;
        cp16(sb + (O_AHI + ra * AS_ST + ca * 8) * 2,
             g_Xh + (row0 + ra) * KPADX + ks + ca * 8);
        cp16(sb + (O_AHI + (ra + 64) * AS_ST + ca * 8) * 2,
             g_Xh + (row0 + ra + 64) * KPADX + ks + ca * 8);
        cp16(sb + (O_BHI + ra * AS_ST + ca * 8) * 2,
             Bh + (size_t)ra * KPADX + ks + ca * 8);
        cp_commit();
    };

    float c[2][4][4];
    #pragma unroll
    for (int mt = 0; mt < 2; ++mt)
        #pragma unroll
        for (int nt = 0; nt < 4; ++nt)
            #pragma unroll
            for (int q = 0; q < 4; ++q) c[mt][nt][q] = 0.f;

    // prologue: stage gs=0..3 into bufs 0..3
    stage(0, 0, 0);
    stage(1, 0, 1);
    stage(2, 0, 2);
    stage(3, 0, 3);
    cp_wait<3>();
    __syncthreads();

    int sl_c = 0, nc_c = 0, buf_c = 0;   // compute cursor (gs)
    int sl_p = 4, nc_p = 0, buf_p = 4;   // prefetch cursor (gs+4)

    #pragma unroll 1
    for (int gs = 0; gs < TOTS; ++gs) {
        const bool do_stage = (gs + 4 < TOTS);
        if (do_stage) stage(sl_p, nc_p, buf_p);

        // ---- compute on buf_c ----
        const uint32_t sb = s_u32 + (uint32_t)buf_c * (STAGE_EL * 2);
        #pragma unroll
        for (int kk = 0; kk < 2; ++kk) {
            uint32_t a[2][4], b[2][4];
            #pragma unroll
            for (int mt = 0; mt < 2; ++mt) {
                uint32_t ao = (uint32_t)(((wm * 32 + 16 * mt + arow_l) * AS_ST
                                          + kk * 16 + acol_l) * 2);
                ldsm_x4(a[mt], sb + O_AHI * 2 + ao);
            }
            #pragma unroll
            for (int nh = 0; nh < 2; ++nh) {
                uint32_t bo = (uint32_t)(((wn * 32 + 16 * nh + brow_l) * AS_ST
                                          + kk * 16 + bcol_l) * 2);
                ldsm_x4(b[nh], sb + O_BHI * 2 + bo);
            }
            #pragma unroll
            for (int mt = 0; mt < 2; ++mt)
                #pragma unroll
                for (int nt = 0; nt < 4; ++nt)
                    mma_f16(c[mt][nt], a[mt],
                            b[nt >> 1][(nt & 1) * 2],
                            b[nt >> 1][(nt & 1) * 2 + 1]);
        }

        // ---- end of chunk: fold with u = 2x - fp16(x), reset accum ----
        if (sl_c == NSLICE - 1) {
            #pragma unroll
            for (int mt = 0; mt < 2; ++mt) {
                const int    r0l = wm * 32 + 16 * mt + g;
                const size_t R0  = row0 + (size_t)r0l;
                #pragma unroll
                for (int nt = 0; nt < 4; ++nt) {
                    int C0 = nc_c * 64 + wn * 32 + 8 * nt + 2 * tg;
                    if (C0 < D_DIM) {
                        if (R0 < (size_t)N) {
                            float2 x0 = __ldg(reinterpret_cast<const float2*>(
                                X + R0 * D_DIM + C0));
                            float u0x = 2.f * x0.x -
                                __half2float(__float2half_rn(x0.x));
                            float u0y = 2.f * x0.y -
                                __half2float(__float2half_rn(x0.y));
                            vp[2 * mt] = fmaf(u0x, c[mt][nt][0],
                                          fmaf(u0y, c[mt][nt][1], vp[2 * mt]));
                            np[2 * mt] = fmaf(x0.x, x0.x,
                                          fmaf(x0.y, x0.y, np[2 * mt]));
                        }
                        if (R0 + 8 < (size_t)N) {
                            float2 x1 = __ldg(reinterpret_cast<const float2*>(
                                X + (R0 + 8) * D_DIM + C0));
                            float u1x = 2.f * x1.x -
                                __half2float(__float2half_rn(x1.x));
                            float u1y = 2.f * x1.y -
                                __half2float(__float2half_rn(x1.y));
                            vp[2 * mt + 1] = fmaf(u1x, c[mt][nt][2],
                                              fmaf(u1y, c[mt][nt][3], vp[2 * mt + 1]));
                            np[2 * mt + 1] = fmaf(x1.x, x1.x,
                                              fmaf(x1.y, x1.y, np[2 * mt + 1]));
                        }
                    }
                    #pragma unroll
                    for (int q = 0; q < 4; ++q) c[mt][nt][q] = 0.f;
                }
            }
        }

        // ---- wait so buffer gs+1 is complete, then publish ----
        if (gs + 4 < TOTS)      cp_wait<3>();
        else if (gs + 3 < TOTS) cp_wait<2>();
        else if (gs + 2 < TOTS) cp_wait<1>();
        else                    cp_wait<0>();
        __syncthreads();

        ++buf_c; if (buf_c == NSTG) buf_c = 0;
        ++buf_p; if (buf_p == NSTG) buf_p = 0;
        ++sl_c;  if (sl_c == NSLICE) { sl_c = 0; ++nc_c; }
        ++sl_p;  if (sl_p == NSLICE) { sl_p = 0; ++nc_p; }
    }

    // reduce across the 4 lanes sharing each row, then smem accumulate
    #pragma unroll
    for (int i = 0; i < 4; ++i) {
        vp[i] += __shfl_xor_sync(0xFFFFFFFFu, vp[i], 1);
        vp[i] += __shfl_xor_sync(0xFFFFFFFFu, vp[i], 2);
        np[i] += __shfl_xor_sync(0xFFFFFFFFu, np[i], 1);
        np[i] += __shfl_xor_sync(0xFFFFFFFFu, np[i], 2);
    }
    if (tg == 0) {
        #pragma unroll
        for (int i = 0; i < 4; ++i) {
            int mt = i >> 1, hi = i & 1;
            int r  = wm * 32 + 16 * mt + 8 * hi + g;
            atomicAdd(&sv[r], vp[i]);
            atomicAdd(&sn[r], np[i]);
        }
    }
    __syncthreads();

    if (tid < BM) {
        size_t row = row0 + (size_t)tid;
        if (row < (size_t)N) {
            float nr = sn[tid];
            if (nr > 0.f)
                atomicAdd(out + __ldg(rowseg + row), sv[tid] / nr);
        }
    }
}

// ---------------------------------------------------------------------------
extern "C" void kernel_launch(void* const* d_in, const int* in_sizes, int n_in,
                              void* d_out, int out_size) {
    const float* X      = (const float*)d_in[0];
    const float* SP     = (const float*)d_in[1];
    const float* W      = (const float*)d_in[2];
    const int*   rowseg = (const int*)  d_in[4];
    const int*   colseg = (const int*)  d_in[5];
    float* out = (float*)d_out;

    const int N = in_sizes[4];   // environments
    const int M = in_sizes[5];   // support points

    // 1) fused prepass: build-Q partials (fast 64x64 tiles) + X->fp16,
    //    running concurrently
    prep_kernel<<<NQB + NSB, 256>>>(X, SP, W, colseg, N, M);

    // 2) reduce Q partials -> fp16; also zero the output vector
    convert_q_kernel<<<NPADQ, KPADX>>>(out, out_size);

    // 3) main fused GEMM + quadratic form + segment reduction
    cudaFuncSetAttribute(gap_mma_kernel,
                         cudaFuncAttributeMaxDynamicSharedMemorySize, SMEM_TOTAL);
    int ntiles = (N + BM - 1) / BM;
    gap_mma_kernel<<<ntiles, 256, SMEM_TOTAL>>>(X, rowseg, out, N);
}